// round 14
// baseline (speedup 1.0000x reference)
#include <cuda_runtime.h>

#define N_EMIT 512
#define ZPL    8
#define ROI    20
#define NPX    400
#define SPL_D  64
#define SPL_H  40
#define SPL_W  40
#define CPW    204    // staged C row pitch (words); 4-aligned for LDS.128

typedef unsigned long long u64;

__device__ __forceinline__ u64 ffma2(u64 a, u64 b, u64 c) {
    u64 d;
    asm("fma.rn.f32x2 %0, %1, %2, %3;" : "=l"(d) : "l"(a), "l"(b), "l"(c));
    return d;
}
__device__ __forceinline__ float fhadd2(u64 a) {
    float lo, hi;
    asm("mov.b64 {%0, %1}, %2;" : "=f"(lo), "=f"(hi) : "l"(a));
    return lo + hi;
}

// per (z,e): dy,dx,dz,scale,bg,ok
__device__ float g_params[ZPL][N_EMIT][8];

// Prep: per z: full-plane coef sums -> per-emitter {dy,dx,dz,scale,bg,ok}.
__global__ __launch_bounds__(512) void prep_kernel(
    const float* __restrict__ pos, const float* __restrict__ inten,
    const float* __restrict__ bg, const float* __restrict__ coefs)
{
    __shared__ float sRed[16][64];
    __shared__ float sCsum[64];
    const int z    = blockIdx.x;
    const int w16  = threadIdx.x >> 5;
    const int lane = threadIdx.x & 31;

    const float* gbase = coefs + ((((size_t)(z + 27) * SPL_H + 9) * SPL_W + 9) << 6);
    float s0 = 0.f, s1 = 0.f;
    #pragma unroll 5
    for (int r = 0; r < 25; r++) {
        int p = w16 * 25 + r;
        int y = p / 20, x = p - y * 20;
        const float* cell = gbase + ((y * SPL_W + x) << 6);
        s0 += cell[lane];
        s1 += cell[lane + 32];
    }
    sRed[w16][lane]      = s0;
    sRed[w16][lane + 32] = s1;
    __syncthreads();
    if (threadIdx.x < 64) {
        float s = 0.f;
        #pragma unroll
        for (int i = 0; i < 16; i++) s += sRed[i][threadIdx.x];
        sCsum[threadIdx.x] = s;
    }
    __syncthreads();

    const int e = threadIdx.x;
    const float p0 = pos[e * 3 + 0];   // Y axis (faithful to reference)
    const float p1 = pos[e * 3 + 1];   // X axis
    const float p2 = pos[e * 3 + 2];   // Z axis

    float pzf = (float)z - p2 + 28.0f;            // SPL_D/2 - ZPL/2
    float fz  = floorf(pzf);
    float dz  = pzf - fz;
    int   iz  = max(0, min((int)fz, SPL_D - 1));

    float py0 = (0.0f - p0) + 10.0f;              // SPL_H/2 - ROI/2
    float fy0 = floorf(py0);
    float dy  = py0 - fy0;
    int   iy0 = (int)fy0;

    float px0 = (0.0f - p1) + 10.0f;              // SPL_W/2 - ROI/2
    float fx0 = floorf(px0);
    float dx  = px0 - fx0;
    int   ix0 = (int)fx0;

    bool ok = (iy0 == 9) && (ix0 == 9) && (iz == z + 27);
    #pragma unroll
    for (int qq = 1; qq < ROI; qq++) {
        ok &= floorf(((float)qq - p0) + 10.0f) == (float)(iy0 + qq);
        ok &= floorf(((float)qq - p1) + 10.0f) == (float)(ix0 + qq);
    }

    float yp[4] = {1.f, dy, dy * dy, dy * dy * dy};
    float xp[4] = {1.f, dx, dx * dx, dx * dx * dx};
    float zp[4] = {1.f, dz, dz * dz, dz * dz * dz};
    float tot = 0.f;
    #pragma unroll
    for (int t = 0; t < 64; t++)
        tot = fmaf(zp[t >> 4] * yp[(t >> 2) & 3] * xp[t & 3], sCsum[t], tot);

    g_params[z][e][0] = dy;
    g_params[z][e][1] = dx;
    g_params[z][e][2] = dz;
    g_params[z][e][3] = inten[e * ZPL + z] / tot;
    g_params[z][e][4] = bg[e * ZPL + z];
    g_params[z][e][5] = ok ? 1.0f : 0.0f;
}

// Main: block = (echunk16, z8, quarter4). grid 512 x 256 threads (8 warps).
// Fast path: t-paired GEMM D[100px,32em]; warp = 4-emitter group, lane = 4-pixel group.
__global__ __launch_bounds__(256) void psf_main(
    const float* __restrict__ pos, const float* __restrict__ inten,
    const float* __restrict__ bg, const float* __restrict__ coefs,
    float* __restrict__ out)
{
    extern __shared__ float dyn[];     // fast: C[32*CPW] ; fallback: sval[100*33]
    __shared__ float sWp[32 * 64];     // (w_even, w_odd) pairs: [tp][2e]
    __shared__ float sScaleF[32], sBgF[32];
    __shared__ float ssumF[4][32];

    const int echunk = blockIdx.x & 15;
    const int z      = (blockIdx.x >> 4) & 7;
    const int q      = blockIdx.x >> 7;
    const int tid    = threadIdx.x;
    const int w8     = tid >> 5;
    const int lane   = tid & 31;
    const int ebase  = echunk * 32;

    const float okf = g_params[z][ebase + lane][5];
    if (!__syncthreads_or(okf == 0.0f)) {
        // ---- W pairs: thread (w8, lane=e) builds t = 8*w8 .. 8*w8+7 ----
        {
            const float dy = g_params[z][ebase + lane][0];
            const float dx = g_params[z][ebase + lane][1];
            const float dz = g_params[z][ebase + lane][2];
            float yp[4] = {1.f, dy, dy * dy, dy * dy * dy};
            float xp[4] = {1.f, dx, dx * dx, dx * dx * dx};
            float zp[4] = {1.f, dz, dz * dz, dz * dz * dz};
            #pragma unroll
            for (int i = 0; i < 4; i++) {
                int t0 = 8 * w8 + 2 * i;
                int t1 = t0 + 1;
                float w0 = zp[t0 >> 4] * yp[(t0 >> 2) & 3] * xp[t0 & 3];
                float w1 = zp[t1 >> 4] * yp[(t1 >> 2) & 3] * xp[t1 & 3];
                *(float2*)&sWp[(4 * w8 + i) * 64 + 2 * lane] = make_float2(w0, w1);
            }
        }
        // ---- stage C: lane = t-pair, split-pair pixel layout ----
        {
            const float* gbase = coefs +
                ((((size_t)(z + 27) * SPL_H + 9) * SPL_W + 9) << 6);
            #pragma unroll
            for (int r = 0; r < 13; r++) {
                int p = w8 * 13 + r;
                if (p < 100) {
                    int P = q * 100 + p;
                    int y = P / 20, x = P - y * 20;
                    const float2* gc = (const float2*)(gbase + ((y * SPL_W + x) << 6));
                    float2 v = gc[lane];                 // (c[p,2*lane], c[p,2*lane+1])
                    int m = p >> 2, d = p & 3;
                    int off = (d < 2) ? (4 * m + 2 * d) : (100 + 4 * m + 2 * (d - 2));
                    *(float2*)&dyn[lane * CPW + off] = v;
                }
            }
        }
        __syncthreads();

        // ---- GEMM: warp w8 = emitters 4*w8..+3, lane(<25) = pixels 4*lane..+3 ----
        if (lane < 25) {
            const int emg = w8;
            const int pg  = lane;

            u64 acc[4][4];
            #pragma unroll
            for (int d = 0; d < 4; d++)
                #pragma unroll
                for (int k = 0; k < 4; k++) acc[d][k] = 0ULL;

            #pragma unroll 8
            for (int tp = 0; tp < 32; tp++) {
                const float* cr = dyn + tp * CPW + 4 * pg;
                ulonglong2 ca = *(const ulonglong2*)cr;          // px 4pg, 4pg+1
                ulonglong2 cb = *(const ulonglong2*)(cr + 100);  // px 4pg+2, 4pg+3
                const float* wr = sWp + tp * 64 + 8 * emg;
                ulonglong2 wa = *(const ulonglong2*)wr;          // em 0,1 of group
                ulonglong2 wb = *(const ulonglong2*)(wr + 4);    // em 2,3
                acc[0][0] = ffma2(ca.x, wa.x, acc[0][0]);
                acc[0][1] = ffma2(ca.x, wa.y, acc[0][1]);
                acc[0][2] = ffma2(ca.x, wb.x, acc[0][2]);
                acc[0][3] = ffma2(ca.x, wb.y, acc[0][3]);
                acc[1][0] = ffma2(ca.y, wa.x, acc[1][0]);
                acc[1][1] = ffma2(ca.y, wa.y, acc[1][1]);
                acc[1][2] = ffma2(ca.y, wb.x, acc[1][2]);
                acc[1][3] = ffma2(ca.y, wb.y, acc[1][3]);
                acc[2][0] = ffma2(cb.x, wa.x, acc[2][0]);
                acc[2][1] = ffma2(cb.x, wa.y, acc[2][1]);
                acc[2][2] = ffma2(cb.x, wb.x, acc[2][2]);
                acc[2][3] = ffma2(cb.x, wb.y, acc[2][3]);
                acc[3][0] = ffma2(cb.y, wa.x, acc[3][0]);
                acc[3][1] = ffma2(cb.y, wa.y, acc[3][1]);
                acc[3][2] = ffma2(cb.y, wb.x, acc[3][2]);
                acc[3][3] = ffma2(cb.y, wb.y, acc[3][3]);
            }

            // ---- Epilogue: hadd pairs, scale+bg, coalesced STG.128 ----
            #pragma unroll
            for (int k = 0; k < 4; k++) {
                const int   e   = ebase + emg * 4 + k;
                const float sc  = g_params[z][e][3];
                const float bgv = g_params[z][e][4];
                float4 v;
                v.x = fhadd2(acc[0][k]);
                v.y = fhadd2(acc[1][k]);
                v.z = fhadd2(acc[2][k]);
                v.w = fhadd2(acc[3][k]);
                v.x = fmaf(v.x, sc, bgv);
                v.y = fmaf(v.y, sc, bgv);
                v.z = fmaf(v.z, sc, bgv);
                v.w = fmaf(v.w, sc, bgv);
                float* op = out + ((size_t)e * ZPL + z) * NPX + q * 100 + 4 * pg;
                *(float4*)op = v;
            }
        }
        return;
    }

    // ---------------- EXACT FALLBACK (bit-faithful per pixel) ----------------
    {
        float* sval = dyn;                 // [100 * 33]
        const int e = ebase + lane;
        const float p0 = pos[e * 3 + 0];
        const float p1 = pos[e * 3 + 1];
        const float p2 = pos[e * 3 + 2];

        float pzf = (float)z - p2 + 28.0f;
        float fz  = floorf(pzf);
        float dz  = pzf - fz;
        int   iz  = max(0, min((int)fz, SPL_D - 1));
        const int izoff = iz * SPL_H;
        float dz2 = dz * dz, dz3 = dz2 * dz;

        float nsum = 0.0f;
        if (w8 < 4) {
            for (int i = 0; i < 100; i++) {
                const int p = w8 * 100 + i;   // warp w8 covers quarter w8 (plane sum)
                const int y = p / 20;
                const int x = p - y * 20;

                float pyf = (float)y - p0 + 10.0f;
                float fy  = floorf(pyf);
                float dyy = pyf - fy;
                int   iy  = max(0, min((int)fy, SPL_H - 1));

                float pxf = (float)x - p1 + 10.0f;
                float fx  = floorf(pxf);
                float dxx = pxf - fx;
                int   ix  = max(0, min((int)fx, SPL_W - 1));

                float dxx2 = dxx * dxx, dxx3 = dxx2 * dxx;
                float dyy2 = dyy * dyy, dyy3 = dyy2 * dyy;

                const float4* cp = (const float4*)(coefs +
                    (((size_t)(izoff + iy) * SPL_W + ix) << 6));

                float s[4];
                #pragma unroll
                for (int a = 0; a < 4; a++) {
                    float4 c0 = cp[a * 4 + 0];
                    float4 c1 = cp[a * 4 + 1];
                    float4 c2 = cp[a * 4 + 2];
                    float4 c3 = cp[a * 4 + 3];
                    float t0 = fmaf(c0.w, dxx3, fmaf(c0.z, dxx2, fmaf(c0.y, dxx, c0.x)));
                    float t1 = fmaf(c1.w, dxx3, fmaf(c1.z, dxx2, fmaf(c1.y, dxx, c1.x)));
                    float t2 = fmaf(c2.w, dxx3, fmaf(c2.z, dxx2, fmaf(c2.y, dxx, c2.x)));
                    float t3 = fmaf(c3.w, dxx3, fmaf(c3.z, dxx2, fmaf(c3.y, dxx, c3.x)));
                    s[a] = fmaf(t3, dyy3, fmaf(t2, dyy2, fmaf(t1, dyy, t0)));
                }
                float v = fmaf(s[3], dz3, fmaf(s[2], dz2, fmaf(s[1], dz, s[0])));

                if (w8 == q) sval[i * 33 + lane] = v;
                nsum += v;
            }
            ssumF[w8][lane] = nsum;
        }
        __syncthreads();
        if (tid < 32) {
            float tot = (ssumF[0][tid] + ssumF[1][tid]) + (ssumF[2][tid] + ssumF[3][tid]);
            int e2 = ebase + tid;
            sScaleF[tid] = inten[e2 * ZPL + z] / tot;
            sBgF[tid]    = bg[e2 * ZPL + z];
        }
        __syncthreads();
        if (w8 < 4) {
            #pragma unroll
            for (int k = 0; k < 8; k++) {
                const int   el  = w8 * 8 + k;
                const int   eo  = ebase + el;
                const float scq = sScaleF[el];
                const float bgv = sBgF[el];
                float* op = out + ((size_t)eo * ZPL + z) * NPX + q * 100;
                #pragma unroll
                for (int m = 0; m < 4; m++) {
                    int pp = m * 32 + lane;
                    if (pp < 100) op[pp] = fmaf(sval[pp * 33 + el], scq, bgv);
                }
            }
        }
    }
}

extern "C" void kernel_launch(void* const* d_in, const int* in_sizes, int n_in,
                              void* d_out, int out_size)
{
    const float* pos   = (const float*)d_in[0];
    const float* inten = (const float*)d_in[1];
    const float* bg    = (const float*)d_in[2];
    const float* coefs = (const float*)d_in[3];

    prep_kernel<<<8, 512>>>(pos, inten, bg, coefs);

    const int smem = 32 * CPW * sizeof(float);   // 26.1 KB dynamic
    psf_main<<<512, 256, smem>>>(pos, inten, bg, coefs, (float*)d_out);
}

// round 16
// speedup vs baseline: 1.4147x; 1.4147x over previous
#include <cuda_runtime.h>

#define N_EMIT 512
#define ZPL    8
#define ROI    20
#define NPX    400
#define SPL_D  64
#define SPL_H  40
#define SPL_W  40
#define CP     404    // staged C_T row pitch (words)
#define TPITCH 33     // fallback sval pitch

typedef unsigned long long u64;

__device__ __forceinline__ u64 ffma2(u64 a, u64 b, u64 c) {
    u64 d;
    asm("fma.rn.f32x2 %0, %1, %2, %3;" : "=l"(d) : "l"(a), "l"(b), "l"(c));
    return d;
}
__device__ __forceinline__ u64 fpack2(float lo, float hi) {
    u64 d;
    asm("mov.b64 %0, {%1, %2};" : "=l"(d) : "f"(lo), "f"(hi));
    return d;
}
__device__ __forceinline__ void funpack2(u64 a, float& lo, float& hi) {
    asm("mov.b64 {%0, %1}, %2;" : "=f"(lo), "=f"(hi) : "l"(a));
}

// One block = (echunk of 32 emitters) x (one z plane). 512 threads = 16 warps.
// Fast path: GEMM D[400,32] = C_T[64,400]^T * W[64,32], tile 8px x 8em (200 threads).
__global__ __launch_bounds__(512, 1) void psf_fused(
    const float* __restrict__ pos,
    const float* __restrict__ inten,
    const float* __restrict__ bg,
    const float* __restrict__ coefs,
    float* __restrict__ out)
{
    extern __shared__ float dyn[];     // fast: C_T[64*CP] ; fallback: sval[NPX*TPITCH]
    __shared__ float sW[64 * 32];      // W[t][e]
    __shared__ float sRed[64][8];
    __shared__ float sCsum[64];
    __shared__ float sScale[32], sBg[32];
    __shared__ int   sOk[16];
    __shared__ float ssum[16][TPITCH]; // fallback only

    const int echunk = blockIdx.x & 15;
    const int z      = blockIdx.x >> 4;
    const int tid    = threadIdx.x;
    const int w      = tid >> 5;
    const int lane   = tid & 31;
    const int ebase  = echunk * 32;

    // ---- Distributed genericity check: warp w checks emitters 2w, 2w+1 ----
    {
        const int ec = ebase + 2 * w + (lane >> 4);
        const float p0 = pos[ec * 3 + 0];   // Y axis (faithful to reference)
        const float p1 = pos[ec * 3 + 1];   // X axis
        const float p2 = pos[ec * 3 + 2];   // Z axis

        float pzf = (float)z - p2 + 28.0f;           // SPL_D/2 - ZPL/2
        float fz  = floorf(pzf);
        int   iz  = max(0, min((int)fz, SPL_D - 1));
        float fy0 = floorf((0.0f - p0) + 10.0f);     // SPL_H/2 - ROI/2
        float fx0 = floorf((0.0f - p1) + 10.0f);     // SPL_W/2 - ROI/2
        bool ok = (iz == z + 27) && (fy0 == 9.0f) && (fx0 == 9.0f);

        int qq = lane & 15;
        if (qq >= 1) {
            ok &= floorf(((float)qq - p0) + 10.0f) == (float)(9 + qq);
            ok &= floorf(((float)qq - p1) + 10.0f) == (float)(9 + qq);
        }
        int q2 = qq + 16;
        if (q2 <= 19) {
            ok &= floorf(((float)q2 - p0) + 10.0f) == (float)(9 + q2);
            ok &= floorf(((float)q2 - p1) + 10.0f) == (float)(9 + q2);
        }
        unsigned m = __ballot_sync(0xffffffffu, ok);
        if (lane == 0) sOk[w] = (m == 0xffffffffu) ? 1 : 0;
    }

    // ---- Stage C_T[t][p ^ sc(t)] (unconditional; fallback just overwrites) ----
    {
        const float* gbase = coefs +
            ((((size_t)(z + 27) * SPL_H + 9) * SPL_W + 9) << 6);
        const int sc1 = (lane >> 3) & 3;
        #pragma unroll 5
        for (int r = 0; r < 25; r++) {
            int p = w * 25 + r;
            int y = p / 20;
            int x = p - y * 20;
            const float* cell = gbase + ((y * SPL_W + x) << 6);
            float v0 = cell[lane];             // coalesced 128B
            float v1 = cell[lane + 32];
            int pp = p ^ sc1;
            dyn[lane * CP + pp]        = v0;
            dyn[(lane + 32) * CP + pp] = v1;
        }
    }
    __syncthreads();

    bool fast;
    {
        int okall = sOk[0];
        #pragma unroll
        for (int i = 1; i < 16; i++) okall &= sOk[i];
        fast = (okall != 0);
    }

    if (fast) {
        // ---- Csum[t] = row sums of staged C (swizzle is a permutation) ----
        {
            const int t   = tid >> 3;
            const int seg = tid & 7;
            const float* row = dyn + t * CP;
            float s = 0.0f;
            for (int g = seg; g < 100; g += 8) {
                float4 c = *(const float4*)(row + 4 * g);
                s += (c.x + c.y) + (c.z + c.w);
            }
            sRed[t][seg] = s;
        }
        __syncthreads();
        if (tid < 64) {
            float s = 0.0f;
            #pragma unroll
            for (int i = 0; i < 8; i++) s += sRed[tid][i];
            sCsum[tid] = s;
        }
        __syncthreads();

        // ---- W[t][e] + plane totals + scale/bg (warp 0, lane = emitter) ----
        if (w == 0) {
            const int e = ebase + lane;
            const float p0 = pos[e * 3 + 0];
            const float p1 = pos[e * 3 + 1];
            const float p2 = pos[e * 3 + 2];
            float pzf = (float)z - p2 + 28.0f;  float dzv = pzf - floorf(pzf);
            float py0 = (0.0f - p0) + 10.0f;    float dyv = py0 - floorf(py0);
            float px0 = (0.0f - p1) + 10.0f;    float dxv = px0 - floorf(px0);
            float xp[4] = {1.0f, dxv, dxv * dxv, dxv * dxv * dxv};
            float yp[4] = {1.0f, dyv, dyv * dyv, dyv * dyv * dyv};
            float zp[4] = {1.0f, dzv, dzv * dzv, dzv * dzv * dzv};
            float tot = 0.0f;
            #pragma unroll
            for (int a = 0; a < 4; a++) {
                #pragma unroll
                for (int b = 0; b < 4; b++) {
                    float wab = zp[a] * yp[b];
                    #pragma unroll
                    for (int c = 0; c < 4; c++) {
                        int t = (a * 4 + b) * 4 + c;
                        float wt = wab * xp[c];
                        sW[t * 32 + lane] = wt;
                        tot = fmaf(wt, sCsum[t], tot);
                    }
                }
            }
            sScale[lane] = inten[e * ZPL + z] / tot;
            sBg[lane]    = bg[e * ZPL + z];
        }
        __syncthreads();

        // ---- GEMM: thread = (emg = tid/50 -> 8 em, pxg = tid%50 -> 8 px) ----
        if (tid < 200) {
            const int emg = tid / 50;
            const int pxg = tid - emg * 50;
            const float* crow = dyn + 8 * pxg;
            const float* wrow = sW + 8 * emg;

            u64 acc[8][4];                       // [local px][em pair]
            #pragma unroll
            for (int d2 = 0; d2 < 8; d2++)
                #pragma unroll
                for (int j = 0; j < 4; j++) acc[d2][j] = 0ULL;

            #pragma unroll 4
            for (int t8 = 0; t8 < 8; t8++) {
                const int sc = t8 & 3;           // compile-time under unroll 4
                #pragma unroll
                for (int u = 0; u < 8; u++) {
                    const int t = t8 * 8 + u;
                    const float* cpt = crow + t * CP;
                    float4 ca = *(const float4*)cpt;         // px 8pxg + (0..3)^sc
                    float4 cb = *(const float4*)(cpt + 4);   // px 8pxg+4 + (0..3)^sc
                    ulonglong2 wv0 = *(const ulonglong2*)(wrow + t * 32);      // em pairs 0,1
                    ulonglong2 wv1 = *(const ulonglong2*)(wrow + t * 32 + 4);  // em pairs 2,3
                    u64 d;
                    d = fpack2(ca.x, ca.x);
                    acc[0 ^ sc][0] = ffma2(d, wv0.x, acc[0 ^ sc][0]);
                    acc[0 ^ sc][1] = ffma2(d, wv0.y, acc[0 ^ sc][1]);
                    acc[0 ^ sc][2] = ffma2(d, wv1.x, acc[0 ^ sc][2]);
                    acc[0 ^ sc][3] = ffma2(d, wv1.y, acc[0 ^ sc][3]);
                    d = fpack2(ca.y, ca.y);
                    acc[1 ^ sc][0] = ffma2(d, wv0.x, acc[1 ^ sc][0]);
                    acc[1 ^ sc][1] = ffma2(d, wv0.y, acc[1 ^ sc][1]);
                    acc[1 ^ sc][2] = ffma2(d, wv1.x, acc[1 ^ sc][2]);
                    acc[1 ^ sc][3] = ffma2(d, wv1.y, acc[1 ^ sc][3]);
                    d = fpack2(ca.z, ca.z);
                    acc[2 ^ sc][0] = ffma2(d, wv0.x, acc[2 ^ sc][0]);
                    acc[2 ^ sc][1] = ffma2(d, wv0.y, acc[2 ^ sc][1]);
                    acc[2 ^ sc][2] = ffma2(d, wv1.x, acc[2 ^ sc][2]);
                    acc[2 ^ sc][3] = ffma2(d, wv1.y, acc[2 ^ sc][3]);
                    d = fpack2(ca.w, ca.w);
                    acc[3 ^ sc][0] = ffma2(d, wv0.x, acc[3 ^ sc][0]);
                    acc[3 ^ sc][1] = ffma2(d, wv0.y, acc[3 ^ sc][1]);
                    acc[3 ^ sc][2] = ffma2(d, wv1.x, acc[3 ^ sc][2]);
                    acc[3 ^ sc][3] = ffma2(d, wv1.y, acc[3 ^ sc][3]);
                    d = fpack2(cb.x, cb.x);
                    acc[4 + (0 ^ sc)][0] = ffma2(d, wv0.x, acc[4 + (0 ^ sc)][0]);
                    acc[4 + (0 ^ sc)][1] = ffma2(d, wv0.y, acc[4 + (0 ^ sc)][1]);
                    acc[4 + (0 ^ sc)][2] = ffma2(d, wv1.x, acc[4 + (0 ^ sc)][2]);
                    acc[4 + (0 ^ sc)][3] = ffma2(d, wv1.y, acc[4 + (0 ^ sc)][3]);
                    d = fpack2(cb.y, cb.y);
                    acc[4 + (1 ^ sc)][0] = ffma2(d, wv0.x, acc[4 + (1 ^ sc)][0]);
                    acc[4 + (1 ^ sc)][1] = ffma2(d, wv0.y, acc[4 + (1 ^ sc)][1]);
                    acc[4 + (1 ^ sc)][2] = ffma2(d, wv1.x, acc[4 + (1 ^ sc)][2]);
                    acc[4 + (1 ^ sc)][3] = ffma2(d, wv1.y, acc[4 + (1 ^ sc)][3]);
                    d = fpack2(cb.z, cb.z);
                    acc[4 + (2 ^ sc)][0] = ffma2(d, wv0.x, acc[4 + (2 ^ sc)][0]);
                    acc[4 + (2 ^ sc)][1] = ffma2(d, wv0.y, acc[4 + (2 ^ sc)][1]);
                    acc[4 + (2 ^ sc)][2] = ffma2(d, wv1.x, acc[4 + (2 ^ sc)][2]);
                    acc[4 + (2 ^ sc)][3] = ffma2(d, wv1.y, acc[4 + (2 ^ sc)][3]);
                    d = fpack2(cb.w, cb.w);
                    acc[4 + (3 ^ sc)][0] = ffma2(d, wv0.x, acc[4 + (3 ^ sc)][0]);
                    acc[4 + (3 ^ sc)][1] = ffma2(d, wv0.y, acc[4 + (3 ^ sc)][1]);
                    acc[4 + (3 ^ sc)][2] = ffma2(d, wv1.x, acc[4 + (3 ^ sc)][2]);
                    acc[4 + (3 ^ sc)][3] = ffma2(d, wv1.y, acc[4 + (3 ^ sc)][3]);
                }
            }

            // ---- Epilogue: unpack em pairs, scale+bg, 2x STG.128 per emitter ----
            #pragma unroll
            for (int j = 0; j < 4; j++) {
                float va[8], vb[8];
                #pragma unroll
                for (int d2 = 0; d2 < 8; d2++) funpack2(acc[d2][j], va[d2], vb[d2]);
                const int el0 = emg * 8 + 2 * j;
                const float s0 = sScale[el0],     b0 = sBg[el0];
                const float s1 = sScale[el0 + 1], b1 = sBg[el0 + 1];
                float* op0 = out + ((size_t)(ebase + el0) * ZPL + z) * NPX + 8 * pxg;
                float* op1 = op0 + (size_t)ZPL * NPX;
                float4 o;
                o.x = fmaf(va[0], s0, b0); o.y = fmaf(va[1], s0, b0);
                o.z = fmaf(va[2], s0, b0); o.w = fmaf(va[3], s0, b0);
                *(float4*)op0 = o;
                o.x = fmaf(va[4], s0, b0); o.y = fmaf(va[5], s0, b0);
                o.z = fmaf(va[6], s0, b0); o.w = fmaf(va[7], s0, b0);
                *(float4*)(op0 + 4) = o;
                o.x = fmaf(vb[0], s1, b1); o.y = fmaf(vb[1], s1, b1);
                o.z = fmaf(vb[2], s1, b1); o.w = fmaf(vb[3], s1, b1);
                *(float4*)op1 = o;
                o.x = fmaf(vb[4], s1, b1); o.y = fmaf(vb[5], s1, b1);
                o.z = fmaf(vb[6], s1, b1); o.w = fmaf(vb[7], s1, b1);
                *(float4*)(op1 + 4) = o;
            }
        }
        return;
    }

    // ---------------- EXACT FALLBACK (bit-faithful per pixel) ----------------
    {
        float* sval = dyn;                 // [NPX * TPITCH]
        const int e = ebase + lane;
        const float p0 = pos[e * 3 + 0];
        const float p1 = pos[e * 3 + 1];
        const float p2 = pos[e * 3 + 2];

        float pzf = (float)z - p2 + 28.0f;
        float fz  = floorf(pzf);
        float dzv = pzf - fz;
        int   iz  = max(0, min((int)fz, SPL_D - 1));
        const int izoff = iz * SPL_H;
        float dz2 = dzv * dzv, dz3 = dz2 * dzv;

        float nsum = 0.0f;
        const int pstart = w * 25;

        for (int i = 0; i < 25; i++) {
            const int p = pstart + i;
            const int y = p / 20;
            const int x = p - y * 20;

            float pyf = (float)y - p0 + 10.0f;
            float fy  = floorf(pyf);
            float dyy = pyf - fy;
            int   iy  = max(0, min((int)fy, SPL_H - 1));

            float pxf = (float)x - p1 + 10.0f;
            float fx  = floorf(pxf);
            float dxx = pxf - fx;
            int   ix  = max(0, min((int)fx, SPL_W - 1));

            float dxx2 = dxx * dxx, dxx3 = dxx2 * dxx;
            float dyy2 = dyy * dyy, dyy3 = dyy2 * dyy;

            const float4* cp = (const float4*)(coefs +
                (((size_t)(izoff + iy) * SPL_W + ix) << 6));

            float s[4];
            #pragma unroll
            for (int a = 0; a < 4; a++) {
                float4 c0 = cp[a * 4 + 0];
                float4 c1 = cp[a * 4 + 1];
                float4 c2 = cp[a * 4 + 2];
                float4 c3 = cp[a * 4 + 3];
                float t0 = fmaf(c0.w, dxx3, fmaf(c0.z, dxx2, fmaf(c0.y, dxx, c0.x)));
                float t1 = fmaf(c1.w, dxx3, fmaf(c1.z, dxx2, fmaf(c1.y, dxx, c1.x)));
                float t2 = fmaf(c2.w, dxx3, fmaf(c2.z, dxx2, fmaf(c2.y, dxx, c2.x)));
                float t3 = fmaf(c3.w, dxx3, fmaf(c3.z, dxx2, fmaf(c3.y, dxx, c3.x)));
                s[a] = fmaf(t3, dyy3, fmaf(t2, dyy2, fmaf(t1, dyy, t0)));
            }
            float v = fmaf(s[3], dz3, fmaf(s[2], dz2, fmaf(s[1], dzv, s[0])));

            sval[p * TPITCH + lane] = v;
            nsum += v;
        }

        ssum[w][lane] = nsum;
        __syncthreads();

        const int el = 2 * w + (lane >> 4);
        float t = ssum[lane & 15][el];
        t += __shfl_xor_sync(0xffffffffu, t, 8);
        t += __shfl_xor_sync(0xffffffffu, t, 4);
        t += __shfl_xor_sync(0xffffffffu, t, 2);
        t += __shfl_xor_sync(0xffffffffu, t, 1);
        const float tot0 = __shfl_sync(0xffffffffu, t, 0);
        const float tot1 = __shfl_sync(0xffffffffu, t, 16);

        #pragma unroll
        for (int q = 0; q < 2; q++) {
            const int   elq = 2 * w + q;
            const int   eo  = ebase + elq;
            const float scq = inten[eo * ZPL + z] / (q ? tot1 : tot0);
            const float bgv = bg[eo * ZPL + z];
            float* op = out + ((size_t)eo * ZPL + z) * NPX;
            #pragma unroll
            for (int m = 0; m < 13; m++) {
                int pp = m * 32 + lane;
                if (pp < NPX) op[pp] = fmaf(sval[pp * TPITCH + elq], scq, bgv);
            }
        }
    }
}

extern "C" void kernel_launch(void* const* d_in, const int* in_sizes, int n_in,
                              void* d_out, int out_size)
{
    const float* pos   = (const float*)d_in[0];
    const float* inten = (const float*)d_in[1];
    const float* bg    = (const float*)d_in[2];
    const float* coefs = (const float*)d_in[3];

    const int smem = 64 * CP * sizeof(float);   // 103.4 KB dynamic
    cudaFuncSetAttribute(psf_fused, cudaFuncAttributeMaxDynamicSharedMemorySize, smem);
    psf_fused<<<128, 512, smem>>>(pos, inten, bg, coefs, (float*)d_out);
}